// round 4
// baseline (speedup 1.0000x reference)
#include <cuda_runtime.h>

// Problem constants
#define NN 50000   // nodes
#define KK 10      // sampled neighbors per node
#define FF 128     // embedding dim
#define HH 64      // hidden per direction
#define GG 256     // 4*H gate width
#define BF 8       // nodes per CTA

typedef unsigned long long u64;

// ---------------- packed f32x2 helpers (sm_103a FFMA2 path) ----------------
__device__ __forceinline__ void fma2(u64& d, u64 a, u64 b) {
    asm("fma.rn.f32x2 %0, %1, %2, %0;" : "+l"(d) : "l"(a), "l"(b));
}
__device__ __forceinline__ u64 add2(u64 a, u64 b) {
    u64 d; asm("add.rn.f32x2 %0, %1, %2;" : "=l"(d) : "l"(a), "l"(b)); return d;
}
__device__ __forceinline__ u64 pack2(float lo, float hi) {
    u64 d;
    asm("mov.b64 %0, {%1, %2};" : "=l"(d)
        : "r"(__float_as_uint(lo)), "r"(__float_as_uint(hi)));
    return d;
}
__device__ __forceinline__ void unpack2(u64 v, float& lo, float& hi) {
    unsigned a, b;
    asm("mov.b64 {%0, %1}, %2;" : "=r"(a), "=r"(b) : "l"(v));
    lo = __uint_as_float(a); hi = __uint_as_float(b);
}

// ---------------- transcendentals (fast, ~1e-6; tolerance is 1e-3) ---------
__device__ __forceinline__ float sigf(float x) {
    return __fdividef(1.0f, 1.0f + __expf(-x));
}
__device__ __forceinline__ float tanh_fast(float x) {
    x = fminf(fmaxf(x, -9.0f), 9.0f);
    float e = __expf(-2.0f * x);
    return __fdividef(1.0f - e, 1.0f + e);
}

// ============================================================================
// Fully fused kernel. One CTA = 8 nodes, 256 threads (warp = node).
//
// Shared memory (floats):
//   x_s    [8][10][128]            10240  gathered embeddings
//   chunk  [32][258]                8256  WihT chunk (transposed, even pad)
//       overlay after both GEMMs:
//       gates [8][256]              2048
//       h_s   [8][64]                512
//   xg     [8][10][256]            20480  input projections + biases
//   whh_s  [256][66]               16896  Whh, even pad for u64 row reads
//   total 55872 floats = 223488 bytes
//
// Column-pair mapping: thread (wid, lane) owns gate-column pairs
//   c = 2*lane + 64*j, c+1   for j = 0..3  (j indexes gate: i, f, g, o)
// so all weight/bias pairs are contiguous 64-bit loads, and the fused
// backward single-step output lands register-resident per thread.
// ============================================================================
#define SM_FLOATS 55872

__global__ __launch_bounds__(256, 1)
void lstm_fused_kernel(const int*   __restrict__ nidx,
                       const float* __restrict__ embed,
                       const float* __restrict__ Wih,
                       const float* __restrict__ Whh,
                       const float* __restrict__ bih,
                       const float* __restrict__ bhh,
                       const float* __restrict__ Wihb,
                       const float* __restrict__ bihb,
                       const float* __restrict__ bhhb,
                       float*       __restrict__ out)
{
    extern __shared__ float sm[];
    float* x_s   = sm;                    // 10240
    float* chunk = sm + 10240;            // 8256
    float* gates = sm + 10240;            // overlay, 2048
    float* h_s   = sm + 12288;            // overlay, 512 (16B aligned)
    float* xg    = sm + 18496;            // 20480
    float* whh_s = sm + 38976;            // 16896

    const int tid  = threadIdx.x;
    const int lane = tid & 31;
    const int wid  = tid >> 5;            // node within CTA
    const int n0   = blockIdx.x * BF;

    // ---- gather embeddings: warp b loads its node's 10 rows (float4) ----
    {
        int idxv = 0;
        if (lane < KK) idxv = nidx[(n0 + wid) * KK + lane];
        #pragma unroll
        for (int k = 0; k < KK; ++k) {
            int row = __shfl_sync(0xffffffffu, idxv, k);
            float4 v = reinterpret_cast<const float4*>(embed)[row * (FF / 4) + lane];
            reinterpret_cast<float4*>(x_s + (wid * KK + k) * FF)[lane] = v;
        }
    }
    // ---- load Whh into padded smem [256][66] ----
    #pragma unroll 8
    for (int i = 0; i < 64; ++i) {
        int e = tid + i * 256;            // e < 16384
        int r = e >> 6, f = e & 63;
        whh_s[r * 66 + f] = Whh[e];
    }
    __syncthreads();

    // =========== forward input-projection GEMM (packed f32x2) ===========
    // acc[k][j] holds cols (2*lane+64j, +1) for node wid, neighbor k.
    u64 acc[KK][4];
    #pragma unroll
    for (int k = 0; k < KK; ++k)
        #pragma unroll
        for (int j = 0; j < 4; ++j) acc[k][j] = 0ull;

    #pragma unroll 1
    for (int cc = 0; cc < 4; ++cc) {
        const int f0 = cc * 32;
        // stage WihT chunk: chunk[ff][c] = Wih[c][f0+ff]
        #pragma unroll 8
        for (int r = 0; r < 32; ++r) {
            int c = wid * 32 + r;
            chunk[lane * 258 + c] = Wih[c * FF + f0 + lane];
        }
        __syncthreads();

        #pragma unroll
        for (int ff4 = 0; ff4 < 8; ++ff4) {
            float4 a4[KK];
            #pragma unroll
            for (int k = 0; k < KK; ++k)
                a4[k] = *reinterpret_cast<const float4*>(
                    x_s + (wid * KK + k) * FF + f0 + ff4 * 4);
            #pragma unroll
            for (int u = 0; u < 4; ++u) {
                u64 w2[4];
                const float* crow = chunk + (ff4 * 4 + u) * 258 + 2 * lane;
                #pragma unroll
                for (int j = 0; j < 4; ++j)
                    w2[j] = *reinterpret_cast<const u64*>(crow + 64 * j);
                #pragma unroll
                for (int k = 0; k < KK; ++k) {
                    float av = (u == 0) ? a4[k].x : (u == 1) ? a4[k].y
                             : (u == 2) ? a4[k].z : a4[k].w;
                    u64 av2 = pack2(av, av);
                    #pragma unroll
                    for (int j = 0; j < 4; ++j) fma2(acc[k][j], av2, w2[j]);
                }
            }
        }
        __syncthreads();
    }

    // ---- epilogue: packed bias add, store xg as 64-bit pairs ----
    {
        u64 bs2[4];
        #pragma unroll
        for (int j = 0; j < 4; ++j) {
            int c = 2 * lane + 64 * j;
            bs2[j] = add2(*reinterpret_cast<const u64*>(bih + c),
                          *reinterpret_cast<const u64*>(bhh + c));
        }
        #pragma unroll
        for (int k = 0; k < KK; ++k)
            #pragma unroll
            for (int j = 0; j < 4; ++j)
                *reinterpret_cast<u64*>(xg + (wid * KK + k) * GG + 2 * lane + 64 * j)
                    = add2(acc[k][j], bs2[j]);
    }

    // =========== fused backward single step (gates i,g,o only) ===========
    // gates_b = x[:,K-1] @ Wihb^T + bihb + bhhb ; f-gate skipped (c0 = 0).
    // jmap: 0 -> i (cols 0:64), 1 -> g (128:192), 2 -> o (192:256)
    {
        u64 accb[3] = {0ull, 0ull, 0ull};
        const int jmap0 = 0, jmap1 = 2, jmap2 = 3;

        #pragma unroll 1
        for (int cc = 0; cc < 4; ++cc) {
            const int f0 = cc * 32;
            #pragma unroll 8
            for (int r = 0; r < 32; ++r) {
                int c = wid * 32 + r;
                chunk[lane * 258 + c] = Wihb[c * FF + f0 + lane];
            }
            __syncthreads();

            const float* xr = x_s + (wid * KK + (KK - 1)) * FF + f0;
            #pragma unroll
            for (int ff4 = 0; ff4 < 8; ++ff4) {
                float4 a4 = *reinterpret_cast<const float4*>(xr + ff4 * 4);
                #pragma unroll
                for (int u = 0; u < 4; ++u) {
                    float av = (u == 0) ? a4.x : (u == 1) ? a4.y
                             : (u == 2) ? a4.z : a4.w;
                    u64 av2 = pack2(av, av);
                    const float* crow = chunk + (ff4 * 4 + u) * 258 + 2 * lane;
                    fma2(accb[0], av2, *reinterpret_cast<const u64*>(crow + 64 * jmap0));
                    fma2(accb[1], av2, *reinterpret_cast<const u64*>(crow + 64 * jmap1));
                    fma2(accb[2], av2, *reinterpret_cast<const u64*>(crow + 64 * jmap2));
                }
            }
            __syncthreads();
        }

        // bias + activation, fully register-resident; write out[:, 64:128]
        int ci = 2 * lane;
        accb[0] = add2(accb[0], add2(*reinterpret_cast<const u64*>(bihb + ci + 64 * jmap0),
                                     *reinterpret_cast<const u64*>(bhhb + ci + 64 * jmap0)));
        accb[1] = add2(accb[1], add2(*reinterpret_cast<const u64*>(bihb + ci + 64 * jmap1),
                                     *reinterpret_cast<const u64*>(bhhb + ci + 64 * jmap1)));
        accb[2] = add2(accb[2], add2(*reinterpret_cast<const u64*>(bihb + ci + 64 * jmap2),
                                     *reinterpret_cast<const u64*>(bhhb + ci + 64 * jmap2)));
        float i0, i1, g0, g1, o0, o1;
        unpack2(accb[0], i0, i1);
        unpack2(accb[1], g0, g1);
        unpack2(accb[2], o0, o1);
        float c0v = sigf(i0) * tanh_fast(g0);
        float c1v = sigf(i1) * tanh_fast(g1);
        float2 hb = make_float2(sigf(o0) * tanh_fast(c0v),
                                sigf(o1) * tanh_fast(c1v));
        *reinterpret_cast<float2*>(out + (n0 + wid) * (2 * HH) + HH + ci) = hb;
    }

    // ---- register-cache this thread's Whh row as 32 packed pairs ----
    u64 wpair[32];
    {
        const u64* wrow = reinterpret_cast<const u64*>(whh_s + tid * 66);
        #pragma unroll
        for (int q = 0; q < 32; ++q) wpair[q] = wrow[q];
    }
    __syncthreads();   // xg visible; chunk reads done -> gates/h_s overlay safe

    // =========== forward recurrence: 10 steps ===========
    float cst0 = 0.0f, cst1 = 0.0f, hout0 = 0.0f, hout1 = 0.0f;

    for (int k = 0; k < KK; ++k) {
        // col phase: thread owns gate column c = tid, all 8 nodes
        float g8[8];
        #pragma unroll
        for (int b = 0; b < 8; ++b) g8[b] = xg[(b * KK + k) * GG + tid];
        if (k > 0) {
            #pragma unroll
            for (int b = 0; b < 8; ++b) {
                const ulonglong2* h2 =
                    reinterpret_cast<const ulonglong2*>(h_s + b * HH);
                u64 s2 = 0ull;
                #pragma unroll
                for (int q = 0; q < 16; ++q) {
                    ulonglong2 hv = h2[q];
                    fma2(s2, wpair[2 * q],     hv.x);
                    fma2(s2, wpair[2 * q + 1], hv.y);
                }
                float sl, sh;
                unpack2(s2, sl, sh);
                g8[b] += sl + sh;
            }
        }
        #pragma unroll
        for (int b = 0; b < 8; ++b) gates[b * GG + tid] = g8[b];
        __syncthreads();

        // cell phase: warp wid owns node wid; lane handles cells lane, lane+32
        {
            float gi0 = gates[wid * GG +   0 + lane];
            float gf0 = gates[wid * GG +  64 + lane];
            float gg0 = gates[wid * GG + 128 + lane];
            float go0 = gates[wid * GG + 192 + lane];
            float gi1 = gates[wid * GG +  32 + lane];
            float gf1 = gates[wid * GG +  96 + lane];
            float gg1 = gates[wid * GG + 160 + lane];
            float go1 = gates[wid * GG + 224 + lane];

            float iv0 = sigf(gi0), fv0 = sigf(gf0), gv0 = tanh_fast(gg0), ov0 = sigf(go0);
            float iv1 = sigf(gi1), fv1 = sigf(gf1), gv1 = tanh_fast(gg1), ov1 = sigf(go1);

            cst0 = (k == 0) ? iv0 * gv0 : fmaf(fv0, cst0, iv0 * gv0);
            cst1 = (k == 0) ? iv1 * gv1 : fmaf(fv1, cst1, iv1 * gv1);
            hout0 = ov0 * tanh_fast(cst0);
            hout1 = ov1 * tanh_fast(cst1);
            h_s[wid * HH +      lane] = hout0;
            h_s[wid * HH + 32 + lane] = hout1;
        }
        __syncthreads();
    }

    // ---- write h_f into out[:, 0:64] ----
    out[(n0 + wid) * (2 * HH) +      lane] = hout0;
    out[(n0 + wid) * (2 * HH) + 32 + lane] = hout1;
}

// ============================================================================
// Launch
// ============================================================================
extern "C" void kernel_launch(void* const* d_in, const int* in_sizes, int n_in,
                              void* d_out, int out_size)
{
    const int*   nidx  = (const int*)  d_in[0];
    const float* embed = (const float*)d_in[1];
    const float* Wih_f = (const float*)d_in[2];
    const float* Whh_f = (const float*)d_in[3];
    const float* bih_f = (const float*)d_in[4];
    const float* bhh_f = (const float*)d_in[5];
    const float* Wih_b = (const float*)d_in[6];
    // d_in[7] = Whh_b: provably unused (backward stream runs exactly one step
    // from h0 = 0, so the recurrent term and the forget gate vanish)
    const float* bih_b = (const float*)d_in[8];
    const float* bhh_b = (const float*)d_in[9];
    float* out = (float*)d_out;

    const size_t smem = SM_FLOATS * sizeof(float);  // 223488 B
    cudaFuncSetAttribute(lstm_fused_kernel,
                         cudaFuncAttributeMaxDynamicSharedMemorySize, (int)smem);

    lstm_fused_kernel<<<NN / BF, 256, smem>>>(nidx, embed,
                                              Wih_f, Whh_f, bih_f, bhh_f,
                                              Wih_b, bih_b, bhh_b, out);
}